// round 2
// baseline (speedup 1.0000x reference)
#include <cuda_runtime.h>
#include <cstdint>

typedef unsigned long long u64;

constexpr int B  = 64;
constexpr int I  = 320;
constexpr int H  = 1536;
constexpr int L  = 3;
constexpr int O  = 256;
constexpr int H3 = 3 * H;

constexpr int KC       = 32;       // k-elements per smem stage
constexpr int KQ       = KC / 4;   // float4 quads per stage (8)
constexpr int TILE_N   = 32;       // output features per block
constexpr int GEMM_THREADS = 128;

// Scratch (no allocations allowed -> __device__ globals)
__device__ float g_inp[B * H];        // current layer input / h
__device__ float g_gh [L * B * H3];   // precomputed hidden-side gates, all layers
__device__ float g_gi [B * H3];       // input-side gates, current layer

// ---------------------------------------------------------------------------
// packed fp32x2 FMA (ptxas never emits FFMA2 from C++; PTX-only, 2x fp32 rate)
// ---------------------------------------------------------------------------
__device__ __forceinline__ u64 ffma2(u64 a, u64 b, u64 c) {
    u64 d;
    asm("fma.rn.f32x2 %0, %1, %2, %3;" : "=l"(d) : "l"(a), "l"(b), "l"(c));
    return d;
}
__device__ __forceinline__ void lds_v2u64(u64& lo, u64& hi, uint32_t addr) {
    asm volatile("ld.shared.v2.b64 {%0, %1}, [%2];" : "=l"(lo), "=l"(hi) : "r"(addr));
}
__device__ __forceinline__ void cp_async16(uint32_t saddr, const void* g) {
    asm volatile("cp.async.cg.shared.global [%0], [%1], 16;" :: "r"(saddr), "l"(g));
}

// ---------------------------------------------------------------------------
// C[b][n] = sum_k A[b][k] * W[n][k] + bias[n]
//   A: [B, K] row-major    W: [N, K] row-major    C: [B, N] row-major
// blockIdx.x tiles N (TILE_N), blockIdx.y = batched layer index (strides).
// Register tile per thread: 4 features x 4 batches, f32x2 accumulators
// (accumulate even/odd k-lanes separately, horizontal add in epilogue).
// ---------------------------------------------------------------------------
__global__ __launch_bounds__(GEMM_THREADS)
void gemm_kernel(const float* __restrict__ A, const float* __restrict__ W,
                 const float* __restrict__ bias, float* __restrict__ C,
                 int K, int N,
                 long strA, long strW, long strB, long strC)
{
    __shared__ float4 shA[2][KQ][B];       // 16 KB
    __shared__ float4 shW[2][KQ][TILE_N];  //  8 KB

    const int l = blockIdx.y;
    A    += (long)l * strA;
    W    += (long)l * strW;
    bias += (long)l * strB;
    C    += (long)l * strC;

    const int n0  = blockIdx.x * TILE_N;
    const int tid = threadIdx.x;
    const int nstages = K / KC;

    const uint32_t aBase = (uint32_t)__cvta_generic_to_shared(&shA[0][0][0]);
    const uint32_t wBase = (uint32_t)__cvta_generic_to_shared(&shW[0][0][0]);
    constexpr uint32_t ABUF = KQ * B * 16;
    constexpr uint32_t WBUF = KQ * TILE_N * 16;

    // load mapping: consecutive threads -> consecutive 16B chunks of one row
    const int lkq  = tid & 7;    // k-quad within stage
    const int lrow = tid >> 3;   // 0..15
    // compute mapping: 8 feature slots x 16 batch groups
    const int fid  = tid & 7;    // features fid + 8*i
    const int bgrp = tid >> 3;   // batches bgrp*4 + j

    auto prefetch = [&](int s) {
        const int k0  = s * KC;
        const int buf = s & 1;
        const uint32_t ab = aBase + buf * ABUF;
        const uint32_t wb = wBase + buf * WBUF;
#pragma unroll
        for (int i = 0; i < 4; ++i) {          // A tile: 64 rows
            const int b = lrow + i * 16;
            cp_async16(ab + (uint32_t)(lkq * B + b) * 16,
                       A + (long)b * K + k0 + lkq * 4);
        }
#pragma unroll
        for (int i = 0; i < 2; ++i) {          // W tile: 32 rows
            const int n = lrow + i * 16;
            cp_async16(wb + (uint32_t)(lkq * TILE_N + n) * 16,
                       W + (long)(n0 + n) * K + k0 + lkq * 4);
        }
    };

    u64 acc[4][4];
#pragma unroll
    for (int i = 0; i < 4; ++i)
#pragma unroll
        for (int j = 0; j < 4; ++j) acc[i][j] = 0ull;

    prefetch(0);
    asm volatile("cp.async.commit_group;");

    for (int s = 0; s < nstages; ++s) {
        if (s + 1 < nstages) prefetch(s + 1);
        asm volatile("cp.async.commit_group;");
        asm volatile("cp.async.wait_group 1;");
        __syncthreads();

        const int buf = s & 1;
        const uint32_t ab = aBase + buf * ABUF + (uint32_t)(bgrp * 4) * 16;
        const uint32_t wb = wBase + buf * WBUF + (uint32_t)fid * 16;

#pragma unroll
        for (int kq = 0; kq < KQ; ++kq) {
            u64 wlo[4], whi[4], alo[4], ahi[4];
#pragma unroll
            for (int i = 0; i < 4; ++i)
                lds_v2u64(wlo[i], whi[i], wb + (uint32_t)(kq * TILE_N + 8 * i) * 16);
#pragma unroll
            for (int j = 0; j < 4; ++j)
                lds_v2u64(alo[j], ahi[j], ab + (uint32_t)(kq * B + j) * 16);
#pragma unroll
            for (int i = 0; i < 4; ++i)
#pragma unroll
                for (int j = 0; j < 4; ++j) {
                    acc[i][j] = ffma2(wlo[i], alo[j], acc[i][j]);
                    acc[i][j] = ffma2(whi[i], ahi[j], acc[i][j]);
                }
        }
        __syncthreads();
    }

    // epilogue: horizontal add + bias
#pragma unroll
    for (int i = 0; i < 4; ++i) {
        const int n  = n0 + fid + 8 * i;
        const float bv = bias[n];
#pragma unroll
        for (int j = 0; j < 4; ++j) {
            const int b = bgrp * 4 + j;
            float lo, hi;
            asm("mov.b64 {%0, %1}, %2;" : "=f"(lo), "=f"(hi) : "l"(acc[i][j]));
            C[(long)b * N + n] = lo + hi + bv;
        }
    }
}

// ---------------------------------------------------------------------------
// GRU gate elementwise:
//   r = sig(i_r + h_r); z = sig(i_z + h_z); n = tanh(i_n + r*h_n)
//   h = (1-z)*n + z*h_prev  -> hidden_out[l] and next layer input
// ---------------------------------------------------------------------------
__global__ void gate_kernel(const float* __restrict__ gi, const float* __restrict__ gh,
                            const float* __restrict__ hprev,
                            float* __restrict__ hid_out, float* __restrict__ inp_next)
{
    const int idx = blockIdx.x * blockDim.x + threadIdx.x;
    if (idx >= B * H) return;
    const int b = idx / H;
    const int j = idx - b * H;
    const long base = (long)b * H3 + j;

    const float ir = gi[base],         hr = gh[base];
    const float iz = gi[base + H],     hz = gh[base + H];
    const float in_ = gi[base + 2*H],  hn = gh[base + 2*H];

    const float r = 1.f / (1.f + __expf(-(ir + hr)));
    const float z = 1.f / (1.f + __expf(-(iz + hz)));
    const float n = tanhf(in_ + r * hn);
    const float hp = hprev[idx];
    const float h = (1.f - z) * n + z * hp;

    hid_out[idx]  = h;
    inp_next[idx] = h;
}

// ---------------------------------------------------------------------------
// h2o: out[b][o] = h[b] . w_h2o[o] + b_h2o[o]   (one warp per output element)
// ---------------------------------------------------------------------------
__global__ void h2o_kernel(const float* __restrict__ h, const float* __restrict__ Wo,
                           const float* __restrict__ bo, float* __restrict__ out)
{
    const int gw   = (blockIdx.x * blockDim.x + threadIdx.x) >> 5;
    const int lane = threadIdx.x & 31;
    if (gw >= B * O) return;
    const int b = gw / O;
    const int o = gw - b * O;

    const float4* hv = (const float4*)(h  + (long)b * H);
    const float4* wv = (const float4*)(Wo + (long)o * H);
    float s = 0.f;
#pragma unroll
    for (int i = lane; i < H / 4; i += 32) {
        const float4 a = hv[i], w = wv[i];
        s += a.x * w.x + a.y * w.y + a.z * w.z + a.w * w.w;
    }
#pragma unroll
    for (int off = 16; off; off >>= 1) s += __shfl_xor_sync(0xFFFFFFFFu, s, off);
    if (lane == 0) out[gw] = s + bo[o];
}

// ---------------------------------------------------------------------------
extern "C" void kernel_launch(void* const* d_in, const int* in_sizes, int n_in,
                              void* d_out, int out_size)
{
    const float* x      = (const float*)d_in[0];
    const float* hidden = (const float*)d_in[1];
    const float* w_i2h  = (const float*)d_in[2];
    const float* b_i2h  = (const float*)d_in[3];
    const float* w_ih   = (const float*)d_in[4];
    const float* w_hh   = (const float*)d_in[5];
    const float* b_ih   = (const float*)d_in[6];
    const float* b_hh   = (const float*)d_in[7];
    const float* w_h2o  = (const float*)d_in[8];
    const float* b_h2o  = (const float*)d_in[9];

    float* out        = (float*)d_out;           // [B, O]
    float* out_hidden = out + B * O;             // [L, B, H]

    float *p_inp, *p_gh, *p_gi;
    cudaGetSymbolAddress((void**)&p_inp, g_inp);
    cudaGetSymbolAddress((void**)&p_gh,  g_gh);
    cudaGetSymbolAddress((void**)&p_gi,  g_gi);

    // 1) inp = x @ w_i2h^T + b_i2h                        (48 blocks)
    gemm_kernel<<<dim3(H / TILE_N, 1), GEMM_THREADS>>>(
        x, w_i2h, b_i2h, p_inp, I, H, 0, 0, 0, 0);

    // 2) gh[l] = hidden[l] @ w_hh[l]^T + b_hh[l], all layers batched (432 blocks)
    gemm_kernel<<<dim3(H3 / TILE_N, L), GEMM_THREADS>>>(
        hidden, w_hh, b_hh, p_gh, H, H3,
        (long)B * H, (long)H3 * H, (long)H3, (long)B * H3);

    // 3) sequential layer chain: gi GEMM + fused gates    (144 blocks each)
    for (int l = 0; l < L; ++l) {
        gemm_kernel<<<dim3(H3 / TILE_N, 1), GEMM_THREADS>>>(
            p_inp, w_ih + (long)l * H3 * H, b_ih + (long)l * H3, p_gi,
            H, H3, 0, 0, 0, 0);
        gate_kernel<<<(B * H + 255) / 256, 256>>>(
            p_gi, p_gh + (long)l * B * H3, hidden + (long)l * B * H,
            out_hidden + (long)l * B * H, p_inp);
    }

    // 4) output = h2 @ w_h2o^T + b_h2o
    h2o_kernel<<<(B * O * 32 + 255) / 256, 256>>>(p_inp, w_h2o, b_h2o, out);
}

// round 3
// speedup vs baseline: 1.5808x; 1.5808x over previous
#include <cuda_runtime.h>
#include <cstdint>

typedef unsigned long long u64;

constexpr int B  = 64;
constexpr int I  = 320;
constexpr int H  = 1536;
constexpr int L  = 3;
constexpr int O  = 256;
constexpr int H3 = 3 * H;

constexpr int KC   = 16;        // k per smem stage
constexpr int TN   = 128;       // features per block tile
constexpr int NT   = 128;       // threads per block
constexpr int WPAD = KC + 4;    // W smem row stride (floats), 16B-aligned

constexpr int S_GI = 8;         // split-K factors
constexpr int S_GH = 4;
constexpr int S_IN = 4;

// ---- scratch (__device__ globals; no allocations allowed) -----------------
__device__ float g_xT  [I * B];                 // x transposed [I][B]
__device__ float g_hT  [L * H * B];             // hidden transposed [L][H][B]
__device__ float g_inpT[H * B];                 // layer input, transposed [H][B]
__device__ float g_pin [S_IN * B * H];          // i2h partials
__device__ float g_pgh [S_GH * L * B * H3];     // hidden-gate partials
__device__ float g_pgi [S_GI * B * H3];         // input-gate partials

// ---------------------------------------------------------------------------
__device__ __forceinline__ u64 ffma2(u64 a, u64 b, u64 c) {
    u64 d;
    asm("fma.rn.f32x2 %0, %1, %2, %3;" : "=l"(d) : "l"(a), "l"(b), "l"(c));
    return d;
}
__device__ __forceinline__ u64 pack2(float x) {
    u64 d;
    asm("mov.b64 %0, {%1, %1};" : "=l"(d) : "f"(x));
    return d;
}
__device__ __forceinline__ void lds_v2u64(u64& lo, u64& hi, uint32_t a) {
    asm volatile("ld.shared.v2.b64 {%0, %1}, [%2];" : "=l"(lo), "=l"(hi) : "r"(a));
}
__device__ __forceinline__ void lds_f2(float& x, float& y, uint32_t a) {
    asm volatile("ld.shared.v2.f32 {%0, %1}, [%2];" : "=f"(x), "=f"(y) : "r"(a));
}
__device__ __forceinline__ void cp16(uint32_t s, const void* g) {
    asm volatile("cp.async.cg.shared.global [%0], [%1], 16;" :: "r"(s), "l"(g));
}

// ---------------------------------------------------------------------------
// part[b][n] = sum_{k in chunk s} AT[k][b] * W[n][k]
//   AT: [K][64] (transposed activations)   W: [N][K] row-major
// Block: TN=128 features x 64 batches. Thread: 8 features x 8 batches,
// batch-paired f32x2 accumulators -> 1.0 B smem per FMA-lane (crossbar-balanced).
// grid = (N/TN, split, layers)
// ---------------------------------------------------------------------------
__global__ __launch_bounds__(NT)
void gemm_kernel(const float* __restrict__ AT, const float* __restrict__ W,
                 float* __restrict__ part,
                 int K, int Kchunk, int N,
                 long strA, long strW, long strPS, long strPL)
{
    __shared__ float shA[2][KC][B];       // 8 KB
    __shared__ float shW[2][TN][WPAD];    // 20 KB

    const int l = blockIdx.z;
    const int s = blockIdx.y;
    AT   += (long)l * strA;
    W    += (long)l * strW;
    part += (long)s * strPS + (long)l * strPL;

    const int n0     = blockIdx.x * TN;
    const int k0base = s * Kchunk;
    const int tid    = threadIdx.x;
    const int fg     = tid & 15;   // feature group: features fg + 16*i
    const int bg     = tid >> 4;   // batch group:   batches  bg*8 .. bg*8+7
    const int nst    = Kchunk / KC;

    const uint32_t aB = (uint32_t)__cvta_generic_to_shared(&shA[0][0][0]);
    const uint32_t wB = (uint32_t)__cvta_generic_to_shared(&shW[0][0][0]);
    constexpr uint32_t ABUF = KC * B * 4;
    constexpr uint32_t WBUF = TN * WPAD * 4;

    auto prefetch = [&](int st) {
        const int k0  = k0base + st * KC;
        const int buf = st & 1;
        const uint32_t ab = aB + buf * ABUF;
        const uint32_t wb = wB + buf * WBUF;
        // A: 16 rows x 16 chunks = 256 chunks, 2 per thread
#pragma unroll
        for (int i = 0; i < 2; ++i) {
            const int c = tid + i * 128;
            const int r = c >> 4, q = c & 15;
            cp16(ab + (uint32_t)(r * B + q * 4) * 4, AT + (long)(k0 + r) * B + q * 4);
        }
        // W: one feature row (KC floats = 4 chunks) per thread
        const float*   wg = W + (long)(n0 + tid) * K + k0;
        const uint32_t ws = wb + (uint32_t)(tid * WPAD) * 4;
#pragma unroll
        for (int q = 0; q < 4; ++q) cp16(ws + q * 16, wg + q * 4);
    };

    u64 acc[8][4];
#pragma unroll
    for (int i = 0; i < 8; ++i)
#pragma unroll
        for (int j = 0; j < 4; ++j) acc[i][j] = 0ull;

    prefetch(0);
    asm volatile("cp.async.commit_group;");

    for (int st = 0; st < nst; ++st) {
        if (st + 1 < nst) prefetch(st + 1);
        asm volatile("cp.async.commit_group;");
        asm volatile("cp.async.wait_group 1;");
        __syncthreads();

        const int buf = st & 1;
        const uint32_t ab = aB + buf * ABUF + (uint32_t)(bg * 8) * 4;
        const uint32_t wb = wB + buf * WBUF + (uint32_t)(fg * WPAD) * 4;

#pragma unroll
        for (int kk = 0; kk < KC / 2; ++kk) {
            const int k = 2 * kk;
            u64 aE[4], aO[4];                       // batch pairs @ k (even) / k+1 (odd)
            lds_v2u64(aE[0], aE[1], ab + (uint32_t)(k * B) * 4);
            lds_v2u64(aE[2], aE[3], ab + (uint32_t)(k * B + 4) * 4);
            lds_v2u64(aO[0], aO[1], ab + (uint32_t)((k + 1) * B) * 4);
            lds_v2u64(aO[2], aO[3], ab + (uint32_t)((k + 1) * B + 4) * 4);
#pragma unroll
            for (int i = 0; i < 8; ++i) {
                float w0, w1;                       // W[f][k], W[f][k+1]
                lds_f2(w0, w1, wb + (uint32_t)(i * 16 * WPAD + k) * 4);
                const u64 wp0 = pack2(w0), wp1 = pack2(w1);
#pragma unroll
                for (int j = 0; j < 4; ++j) {
                    acc[i][j] = ffma2(wp0, aE[j], acc[i][j]);
                    acc[i][j] = ffma2(wp1, aO[j], acc[i][j]);
                }
            }
        }
        __syncthreads();
    }

    // epilogue: write fp32 partials
#pragma unroll
    for (int i = 0; i < 8; ++i) {
        const int f = n0 + fg + 16 * i;
#pragma unroll
        for (int j = 0; j < 4; ++j) {
            float c0, c1;
            asm("mov.b64 {%0, %1}, %2;" : "=f"(c0), "=f"(c1) : "l"(acc[i][j]));
            const int b = bg * 8 + 2 * j;
            part[(long)b * N + f]       = c0;
            part[(long)(b + 1) * N + f] = c1;
        }
    }
}

// ---------------------------------------------------------------------------
// [rows][cols] -> [cols][rows], batched over blockIdx.y with strides
// ---------------------------------------------------------------------------
__global__ void transpose_kernel(const float* __restrict__ src, float* __restrict__ dst,
                                 int rows, int cols, long srcStr, long dstStr)
{
    const int l = blockIdx.y;
    src += (long)l * srcStr;
    dst += (long)l * dstStr;
    const int idx = blockIdx.x * blockDim.x + threadIdx.x;
    if (idx >= rows * cols) return;
    const int r = idx / cols, c = idx - r * cols;
    dst[(long)c * rows + r] = src[idx];
}

// ---------------------------------------------------------------------------
// inpT[j][b] = b_i2h[j] + sum_s pin[s][b][j]
// ---------------------------------------------------------------------------
__global__ void reduce_inp_kernel(const float* __restrict__ part,
                                  const float* __restrict__ bias,
                                  float* __restrict__ inpT)
{
    const int idx = blockIdx.x * blockDim.x + threadIdx.x;
    if (idx >= H * B) return;
    const int j = idx >> 6, b = idx & 63;
    float s = bias[j];
#pragma unroll
    for (int k = 0; k < S_IN; ++k)
        s += part[(long)k * B * H + (long)b * H + j];
    inpT[idx] = s;                       // idx = j*B + b  (transposed layout)
}

// ---------------------------------------------------------------------------
// GRU gates + split-K reduction + bias. Writes hid_out [B][H] and inpT [H][B].
// ---------------------------------------------------------------------------
__global__ void gate_kernel(const float* __restrict__ pgi, const float* __restrict__ pgh,
                            const float* __restrict__ bih, const float* __restrict__ bhh,
                            const float* __restrict__ hprev,
                            float* __restrict__ hid_out, float* __restrict__ inpT)
{
    const int idx = blockIdx.x * blockDim.x + threadIdx.x;
    if (idx >= B * H) return;
    const int b = idx / H;
    const int j = idx - b * H;
    const long base = (long)b * H3 + j;

    float ir = bih[j], iz = bih[j + H], in_ = bih[j + 2 * H];
#pragma unroll
    for (int s = 0; s < S_GI; ++s) {
        const float* p = pgi + (long)s * B * H3 + base;
        ir += p[0]; iz += p[H]; in_ += p[2 * H];
    }
    float hr = bhh[j], hz = bhh[j + H], hn = bhh[j + 2 * H];
#pragma unroll
    for (int s = 0; s < S_GH; ++s) {
        const float* p = pgh + (long)s * (L * B * H3) + base;
        hr += p[0]; hz += p[H]; hn += p[2 * H];
    }

    const float r = 1.f / (1.f + __expf(-(ir + hr)));
    const float z = 1.f / (1.f + __expf(-(iz + hz)));
    const float n = tanhf(in_ + r * hn);
    const float h = (1.f - z) * n + z * hprev[idx];

    hid_out[idx]            = h;
    inpT[(long)j * B + b]   = h;
}

// ---------------------------------------------------------------------------
// h2o: one warp per (b, o)
// ---------------------------------------------------------------------------
__global__ void h2o_kernel(const float* __restrict__ h, const float* __restrict__ Wo,
                           const float* __restrict__ bo, float* __restrict__ out)
{
    const int gw   = (blockIdx.x * blockDim.x + threadIdx.x) >> 5;
    const int lane = threadIdx.x & 31;
    if (gw >= B * O) return;
    const int b = gw / O;
    const int o = gw - b * O;

    const float4* hv = (const float4*)(h  + (long)b * H);
    const float4* wv = (const float4*)(Wo + (long)o * H);
    float s = 0.f;
#pragma unroll
    for (int i = lane; i < H / 4; i += 32) {
        const float4 a = hv[i], w = wv[i];
        s += a.x * w.x + a.y * w.y + a.z * w.z + a.w * w.w;
    }
#pragma unroll
    for (int off = 16; off; off >>= 1) s += __shfl_xor_sync(0xFFFFFFFFu, s, off);
    if (lane == 0) out[gw] = s + bo[o];
}

// ---------------------------------------------------------------------------
extern "C" void kernel_launch(void* const* d_in, const int* in_sizes, int n_in,
                              void* d_out, int out_size)
{
    const float* x      = (const float*)d_in[0];
    const float* hidden = (const float*)d_in[1];
    const float* w_i2h  = (const float*)d_in[2];
    const float* b_i2h  = (const float*)d_in[3];
    const float* w_ih   = (const float*)d_in[4];
    const float* w_hh   = (const float*)d_in[5];
    const float* b_ih   = (const float*)d_in[6];
    const float* b_hh   = (const float*)d_in[7];
    const float* w_h2o  = (const float*)d_in[8];
    const float* b_h2o  = (const float*)d_in[9];

    float* out        = (float*)d_out;       // [B, O]
    float* out_hidden = out + B * O;         // [L, B, H]

    float *xT, *hT, *inpT, *pin, *pgh, *pgi;
    cudaGetSymbolAddress((void**)&xT,   g_xT);
    cudaGetSymbolAddress((void**)&hT,   g_hT);
    cudaGetSymbolAddress((void**)&inpT, g_inpT);
    cudaGetSymbolAddress((void**)&pin,  g_pin);
    cudaGetSymbolAddress((void**)&pgh,  g_pgh);
    cudaGetSymbolAddress((void**)&pgi,  g_pgi);

    // transposes: x -> [I][B], hidden -> [L][H][B]
    transpose_kernel<<<dim3((B * I + 255) / 256, 1), 256>>>(x, xT, B, I, 0, 0);
    transpose_kernel<<<dim3((B * H + 255) / 256, L), 256>>>(hidden, hT, B, H,
                                                            (long)B * H, (long)H * B);

    // i2h partials: K=320, chunk 80 (5 stages), grid (12, 4, 1)
    gemm_kernel<<<dim3(H / TN, S_IN, 1), NT>>>(
        xT, w_i2h, pin, I, I / S_IN, H, 0, 0, (long)B * H, 0);
    reduce_inp_kernel<<<(H * B + 255) / 256, 256>>>(pin, b_i2h, inpT);

    // gh partials, all layers: K=1536, chunk 384 (24 stages), grid (36, 4, 3) = 432 blocks
    gemm_kernel<<<dim3(H3 / TN, S_GH, L), NT>>>(
        hT, w_hh, pgh, H, H / S_GH, H3,
        (long)H * B, (long)H3 * H, (long)L * B * H3, (long)B * H3);

    // sequential layer chain: gi partials (chunk 192, 12 stages, 288 blocks) + gates
    for (int l = 0; l < L; ++l) {
        gemm_kernel<<<dim3(H3 / TN, S_GI, 1), NT>>>(
            inpT, w_ih + (long)l * H3 * H, pgi, H, H / S_GI, H3,
            0, 0, (long)B * H3, 0);
        gate_kernel<<<(B * H + 255) / 256, 256>>>(
            pgi, pgh + (long)l * B * H3,
            b_ih + (long)l * H3, b_hh + (long)l * H3,
            hidden + (long)l * B * H,
            out_hidden + (long)l * B * H, inpT);
    }

    // output = h2 @ w_h2o^T + b_h2o  (h2 = out_hidden layer 2, [B][H])
    h2o_kernel<<<(B * O * 32 + 255) / 256, 256>>>(
        out_hidden + (long)2 * B * H, w_h2o, b_h2o, out);
}

// round 5
// speedup vs baseline: 1.6380x; 1.0362x over previous
#include <cuda_runtime.h>
#include <cuda_bf16.h>
#include <cstdint>

typedef unsigned long long u64;

constexpr int B  = 64;
constexpr int I  = 320;
constexpr int H  = 1536;
constexpr int L  = 3;
constexpr int O  = 256;
constexpr int H3 = 3 * H;

constexpr int TM = 128;    // feature tile (M)
constexpr int TB = 64;     // batch tile (N)
constexpr int KC = 64;     // k per stage
constexpr int NT = 256;    // threads
constexpr int S_GI = 4;
constexpr int S_GH = 2;

constexpr int      SWB    = 144;                 // smem row stride bytes (72 bf16)
constexpr uint32_t OFF_WH = 0;
constexpr uint32_t OFF_WL = 128 * SWB;           // 18432
constexpr uint32_t OFF_AH = 2 * 128 * SWB;       // 36864
constexpr uint32_t OFF_AL = OFF_AH + 64 * SWB;   // 46080
constexpr uint32_t BUFSZ  = OFF_AL + 64 * SWB;   // 55296
constexpr uint32_t DSMEM  = 2 * BUFSZ;           // 110592

// ---- scratch ---------------------------------------------------------------
__device__ float g_inp[B * H];
__device__ float g_pin[B * H];
__device__ float g_pgh[L * S_GH * B * H3];
__device__ float g_pgi[S_GI * B * H3];

// ---- helpers ---------------------------------------------------------------
__device__ __forceinline__ uint32_t smem_u32(const void* p) {
    return (uint32_t)__cvta_generic_to_shared(p);
}
__device__ __forceinline__ void sts128(uint32_t a, uint32_t x, uint32_t y,
                                       uint32_t z, uint32_t w) {
    asm volatile("st.shared.v4.b32 [%0], {%1,%2,%3,%4};"
                 :: "r"(a), "r"(x), "r"(y), "r"(z), "r"(w) : "memory");
}
#define LDSM_X4(r, addr)                                                       \
    asm volatile("ldmatrix.sync.aligned.m8n8.x4.shared.b16 {%0,%1,%2,%3}, [%4];" \
        : "=r"((r)[0]), "=r"((r)[1]), "=r"((r)[2]), "=r"((r)[3]) : "r"(addr))

#define MMA_BF16(d, a, b0, b1)                                                 \
    asm volatile("mma.sync.aligned.m16n8k16.row.col.f32.bf16.bf16.f32 "        \
        "{%0,%1,%2,%3}, {%4,%5,%6,%7}, {%8,%9}, {%0,%1,%2,%3};"                \
        : "+f"((d)[0]), "+f"((d)[1]), "+f"((d)[2]), "+f"((d)[3])               \
        : "r"((a)[0]), "r"((a)[1]), "r"((a)[2]), "r"((a)[3]), "r"(b0), "r"(b1))

__device__ __forceinline__ void cvt_hilo8(const float* f, uint32_t* hi, uint32_t* lo) {
    // 8 fp32 -> 4 b32 of bf16 hi pairs + 4 b32 of lo pairs
#pragma unroll
    for (int p = 0; p < 4; ++p) {
        float a = f[2 * p], b = f[2 * p + 1];
        __nv_bfloat16 ha = __float2bfloat16_rn(a);
        __nv_bfloat16 hb = __float2bfloat16_rn(b);
        __nv_bfloat16 la = __float2bfloat16_rn(a - __bfloat162float(ha));
        __nv_bfloat16 lb = __float2bfloat16_rn(b - __bfloat162float(hb));
        hi[p] = (uint32_t)__bfloat16_as_ushort(ha) |
                ((uint32_t)__bfloat16_as_ushort(hb) << 16);
        lo[p] = (uint32_t)__bfloat16_as_ushort(la) |
                ((uint32_t)__bfloat16_as_ushort(lb) << 16);
    }
}

// ---------------------------------------------------------------------------
// part[b][n] = sum_{k in chunk} A[b][k] * W[n][k]   (bf16 hi/lo compensated)
//   A: [64][K] fp32 row-major   W: [N][K] fp32 row-major
// grid = (N/TM, split, layer)
// ---------------------------------------------------------------------------
__global__ __launch_bounds__(NT)
void mma_gemm(const float* __restrict__ Ag, const float* __restrict__ Wg,
              float* __restrict__ part, int K, int Kchunk, int N,
              long strA, long strW, long strPS, long strPL)
{
    extern __shared__ char dsm[];
    const uint32_t base = smem_u32(dsm);

    const int l  = blockIdx.z;
    const int sp = blockIdx.y;
    Ag   += (long)l * strA;
    Wg   += (long)l * strW;
    part += (long)l * strPL + (long)sp * strPS;

    const int n0   = blockIdx.x * TM;
    const int tid  = threadIdx.x;
    const int wid  = tid >> 5;
    const int lane = tid & 31;

    const int fm = (wid & 3) * 32;   // warp feature offset (M)
    const int bn = (wid >> 2) * 32;  // warp batch offset (N)

    // fill mappings
    const int wr = tid >> 1, wh = tid & 1;   // W: row, 32-col half
    const int ar = tid >> 2, aq = tid & 3;   // A: row, 16-col quarter

    // ldmatrix lane base offsets (bytes, within plane)
    uint32_t wrow[2], arow[2];
#pragma unroll
    for (int mt = 0; mt < 2; ++mt)
        wrow[mt] = (uint32_t)((fm + mt * 16 + ((lane >> 3) & 1) * 8 + (lane & 7)) * SWB
                              + (lane >> 4) * 16);
#pragma unroll
    for (int ng = 0; ng < 2; ++ng)
        arow[ng] = (uint32_t)((bn + ng * 16 + (lane >> 4) * 8 + (lane & 7)) * SWB
                              + ((lane >> 3) & 1) * 16);

    const int nst    = Kchunk / KC;
    const int k0base = sp * Kchunk;

    float4 wv[8], av[4];             // gmem staging
    float  d[2][4][4];
#pragma unroll
    for (int mt = 0; mt < 2; ++mt)
#pragma unroll
        for (int nt = 0; nt < 4; ++nt)
#pragma unroll
            for (int i = 0; i < 4; ++i) d[mt][nt][i] = 0.f;

    auto ldg_stage = [&](int st) {
        const int k0 = k0base + st * KC;
        const float4* ws = (const float4*)(Wg + (long)(n0 + wr) * K + k0 + wh * 32);
#pragma unroll
        for (int q = 0; q < 8; ++q) wv[q] = ws[q];
        const float4* as = (const float4*)(Ag + (long)ar * K + k0 + aq * 16);
#pragma unroll
        for (int q = 0; q < 4; ++q) av[q] = as[q];
    };

    auto store_stage = [&](int buf) {
        const uint32_t bb = base + (uint32_t)buf * BUFSZ;
        const uint32_t wdst = bb + (uint32_t)(wr * SWB + wh * 64);
#pragma unroll
        for (int g = 0; g < 4; ++g) {
            float f[8] = { wv[2*g].x, wv[2*g].y, wv[2*g].z, wv[2*g].w,
                           wv[2*g+1].x, wv[2*g+1].y, wv[2*g+1].z, wv[2*g+1].w };
            uint32_t hi[4], lo[4];
            cvt_hilo8(f, hi, lo);
            sts128(wdst + OFF_WH + g * 16, hi[0], hi[1], hi[2], hi[3]);
            sts128(wdst + OFF_WL + g * 16, lo[0], lo[1], lo[2], lo[3]);
        }
        const uint32_t adst = bb + (uint32_t)(ar * SWB + aq * 32);
#pragma unroll
        for (int g = 0; g < 2; ++g) {
            float f[8] = { av[2*g].x, av[2*g].y, av[2*g].z, av[2*g].w,
                           av[2*g+1].x, av[2*g+1].y, av[2*g+1].z, av[2*g+1].w };
            uint32_t hi[4], lo[4];
            cvt_hilo8(f, hi, lo);
            sts128(adst + OFF_AH + g * 16, hi[0], hi[1], hi[2], hi[3]);
            sts128(adst + OFF_AL + g * 16, lo[0], lo[1], lo[2], lo[3]);
        }
    };

    auto compute_stage = [&](int buf) {
        const uint32_t bb = base + (uint32_t)buf * BUFSZ;
#pragma unroll
        for (int ks = 0; ks < KC / 16; ++ks) {
            const uint32_t kb = (uint32_t)(ks * 32);
            uint32_t whf[2][4], wlf[2][4], ahf[2][4], alf[2][4];
#pragma unroll
            for (int mt = 0; mt < 2; ++mt) {
                LDSM_X4(whf[mt], bb + OFF_WH + wrow[mt] + kb);
                LDSM_X4(wlf[mt], bb + OFF_WL + wrow[mt] + kb);
            }
#pragma unroll
            for (int ng = 0; ng < 2; ++ng) {
                LDSM_X4(ahf[ng], bb + OFF_AH + arow[ng] + kb);
                LDSM_X4(alf[ng], bb + OFF_AL + arow[ng] + kb);
            }
#pragma unroll
            for (int mt = 0; mt < 2; ++mt)
#pragma unroll
                for (int nt = 0; nt < 4; ++nt) {
                    const int ng = nt >> 1, hf = (nt & 1) * 2;
                    MMA_BF16(d[mt][nt], whf[mt], ahf[ng][hf], ahf[ng][hf + 1]);
                    MMA_BF16(d[mt][nt], wlf[mt], ahf[ng][hf], ahf[ng][hf + 1]);
                    MMA_BF16(d[mt][nt], whf[mt], alf[ng][hf], alf[ng][hf + 1]);
                }
        }
    };

    ldg_stage(0);
    store_stage(0);
    for (int st = 0; st < nst; ++st) {
        if (st + 1 < nst) ldg_stage(st + 1);
        __syncthreads();
        compute_stage(st & 1);
        if (st + 1 < nst) store_stage((st + 1) & 1);
    }

    // epilogue: C[m16n8] frag -> part[b][f]
#pragma unroll
    for (int mt = 0; mt < 2; ++mt)
#pragma unroll
        for (int nt = 0; nt < 4; ++nt)
#pragma unroll
            for (int i = 0; i < 4; ++i) {
                const int f = n0 + fm + mt * 16 + (lane >> 2) + (i >= 2 ? 8 : 0);
                const int b = bn + nt * 8 + (lane & 3) * 2 + (i & 1);
                part[(long)b * N + f] = d[mt][nt][i];
            }
}

// ---------------------------------------------------------------------------
__global__ void reduce_inp_kernel(const float* __restrict__ part,
                                  const float* __restrict__ bias,
                                  float* __restrict__ inp)
{
    const int idx = blockIdx.x * blockDim.x + threadIdx.x;
    if (idx >= B * H) return;
    inp[idx] = part[idx] + bias[idx % H];
}

// ---------------------------------------------------------------------------
__global__ void gate_kernel(const float* __restrict__ pgi, const float* __restrict__ pgh,
                            const float* __restrict__ bih, const float* __restrict__ bhh,
                            const float* __restrict__ hprev, float* __restrict__ hid_out)
{
    const int idx = blockIdx.x * blockDim.x + threadIdx.x;
    if (idx >= B * H) return;
    const int b = idx / H;
    const int j = idx - b * H;
    const long base = (long)b * H3 + j;

    float ir = bih[j], iz = bih[j + H], in_ = bih[j + 2 * H];
#pragma unroll
    for (int s = 0; s < S_GI; ++s) {
        const float* p = pgi + (long)s * B * H3 + base;
        ir += p[0]; iz += p[H]; in_ += p[2 * H];
    }
    float hr = bhh[j], hz = bhh[j + H], hn = bhh[j + 2 * H];
#pragma unroll
    for (int s = 0; s < S_GH; ++s) {
        const float* p = pgh + (long)s * B * H3 + base;
        hr += p[0]; hz += p[H]; hn += p[2 * H];
    }

    const float r = 1.f / (1.f + __expf(-(ir + hr)));
    const float z = 1.f / (1.f + __expf(-(iz + hz)));
    const float n = tanhf(in_ + r * hn);
    hid_out[idx] = (1.f - z) * n + z * hprev[idx];
}

// ---------------------------------------------------------------------------
__global__ void h2o_kernel(const float* __restrict__ h, const float* __restrict__ Wo,
                           const float* __restrict__ bo, float* __restrict__ out)
{
    const int gw   = (blockIdx.x * blockDim.x + threadIdx.x) >> 5;
    const int lane = threadIdx.x & 31;
    if (gw >= B * O) return;
    const int b = gw / O;
    const int o = gw - b * O;

    const float4* hv = (const float4*)(h  + (long)b * H);
    const float4* wv = (const float4*)(Wo + (long)o * H);
    float s = 0.f;
#pragma unroll
    for (int i = lane; i < H / 4; i += 32) {
        const float4 a = hv[i], w = wv[i];
        s += a.x * w.x + a.y * w.y + a.z * w.z + a.w * w.w;
    }
#pragma unroll
    for (int off = 16; off; off >>= 1) s += __shfl_xor_sync(0xFFFFFFFFu, s, off);
    if (lane == 0) out[gw] = s + bo[o];
}

// ---------------------------------------------------------------------------
extern "C" void kernel_launch(void* const* d_in, const int* in_sizes, int n_in,
                              void* d_out, int out_size)
{
    const float* x      = (const float*)d_in[0];
    const float* hidden = (const float*)d_in[1];
    const float* w_i2h  = (const float*)d_in[2];
    const float* b_i2h  = (const float*)d_in[3];
    const float* w_ih   = (const float*)d_in[4];
    const float* w_hh   = (const float*)d_in[5];
    const float* b_ih   = (const float*)d_in[6];
    const float* b_hh   = (const float*)d_in[7];
    const float* w_h2o  = (const float*)d_in[8];
    const float* b_h2o  = (const float*)d_in[9];

    float* out        = (float*)d_out;       // [B, O]
    float* out_hidden = out + B * O;         // [L, B, H]

    float *inp, *pin, *pgh, *pgi;
    cudaGetSymbolAddress((void**)&inp, g_inp);
    cudaGetSymbolAddress((void**)&pin, g_pin);
    cudaGetSymbolAddress((void**)&pgh, g_pgh);
    cudaGetSymbolAddress((void**)&pgi, g_pgi);

    cudaFuncSetAttribute(mma_gemm, cudaFuncAttributeMaxDynamicSharedMemorySize, DSMEM);

    // 1) i2h: pin = x @ w_i2h^T                    (12 blocks, K=320)
    mma_gemm<<<dim3(H / TM, 1, 1), NT, DSMEM>>>(
        x, w_i2h, pin, I, I, H, 0, 0, 0, 0);
    reduce_inp_kernel<<<(B * H + 255) / 256, 256>>>(pin, b_i2h, inp);

    // 2) gh partials, all layers (36 x 2 x 3 = 216 blocks)
    mma_gemm<<<dim3(H3 / TM, S_GH, L), NT, DSMEM>>>(
        hidden, w_hh, pgh, H, H / S_GH, H3,
        (long)B * H, (long)H3 * H, (long)B * H3, (long)S_GH * B * H3);

    // 3) sequential layer chain (gi: 36 x 4 = 144 blocks each)
    for (int l = 0; l < L; ++l) {
        const float* A = (l == 0) ? inp : out_hidden + (long)(l - 1) * B * H;
        mma_gemm<<<dim3(H3 / TM, S_GI, 1), NT, DSMEM>>>(
            A, w_ih + (long)l * H3 * H, pgi, H, H / S_GI, H3,
            0, 0, (long)B * H3, 0);
        gate_kernel<<<(B * H + 255) / 256, 256>>>(
            pgi, pgh + (long)l * S_GH * B * H3,
            b_ih + (long)l * H3, b_hh + (long)l * H3,
            hidden + (long)l * B * H, out_hidden + (long)l * B * H);
    }

    // 4) output = h2 @ w_h2o^T + b_h2o
    h2o_kernel<<<(B * O * 32 + 255) / 256, 256>>>(
        out_hidden + (long)2 * B * H, w_h2o, b_h2o, out);
}

// round 6
// speedup vs baseline: 2.2193x; 1.3549x over previous
#include <cuda_runtime.h>
#include <cuda_bf16.h>
#include <cstdint>

typedef unsigned long long u64;

constexpr int B  = 64;
constexpr int I  = 320;
constexpr int H  = 1536;
constexpr int L  = 3;
constexpr int O  = 256;
constexpr int H3 = 3 * H;

constexpr int TM = 128;    // feature tile (M)
constexpr int KC = 32;     // k per stage
constexpr int NT = 256;    // threads
constexpr int S_GI = 8;    // split-K for serial gi layers
constexpr int S_MG = 2;    // split-K for merged gh+gi0 launch
constexpr int S_IN = 5;    // split-K for i2h (K=320 -> chunks of 64)

constexpr int      SWB    = 80;                  // smem row stride bytes (32 bf16 + pad)
constexpr uint32_t OFF_WH = 0;
constexpr uint32_t OFF_WL = 128 * SWB;           // 10240
constexpr uint32_t OFF_AH = 2 * 128 * SWB;       // 20480
constexpr uint32_t OFF_AL = OFF_AH + 64 * SWB;   // 25600
constexpr uint32_t BUFSZ  = OFF_AL + 64 * SWB;   // 30720
constexpr uint32_t DSMEM  = 2 * BUFSZ;           // 61440 -> 2 CTAs/SM

// ---- scratch ---------------------------------------------------------------
__device__ float g_inp[B * H];
__device__ float g_pin[S_IN * B * H];
__device__ float g_pgh[L * S_MG * B * H3];
__device__ float g_pgi[S_GI * B * H3];

// ---- helpers ---------------------------------------------------------------
__device__ __forceinline__ uint32_t smem_u32(const void* p) {
    return (uint32_t)__cvta_generic_to_shared(p);
}
__device__ __forceinline__ void sts128(uint32_t a, uint32_t x, uint32_t y,
                                       uint32_t z, uint32_t w) {
    asm volatile("st.shared.v4.b32 [%0], {%1,%2,%3,%4};"
                 :: "r"(a), "r"(x), "r"(y), "r"(z), "r"(w) : "memory");
}
#define LDSM_X4(r, addr)                                                       \
    asm volatile("ldmatrix.sync.aligned.m8n8.x4.shared.b16 {%0,%1,%2,%3}, [%4];" \
        : "=r"((r)[0]), "=r"((r)[1]), "=r"((r)[2]), "=r"((r)[3]) : "r"(addr))

#define MMA_BF16(d, a, b0, b1)                                                 \
    asm volatile("mma.sync.aligned.m16n8k16.row.col.f32.bf16.bf16.f32 "        \
        "{%0,%1,%2,%3}, {%4,%5,%6,%7}, {%8,%9}, {%0,%1,%2,%3};"                \
        : "+f"((d)[0]), "+f"((d)[1]), "+f"((d)[2]), "+f"((d)[3])               \
        : "r"((a)[0]), "r"((a)[1]), "r"((a)[2]), "r"((a)[3]), "r"(b0), "r"(b1))

__device__ __forceinline__ void cvt_hilo8(const float* f, uint32_t* hi, uint32_t* lo) {
#pragma unroll
    for (int p = 0; p < 4; ++p) {
        float a = f[2 * p], b = f[2 * p + 1];
        __nv_bfloat16 ha = __float2bfloat16_rn(a);
        __nv_bfloat16 hb = __float2bfloat16_rn(b);
        __nv_bfloat16 la = __float2bfloat16_rn(a - __bfloat162float(ha));
        __nv_bfloat16 lb = __float2bfloat16_rn(b - __bfloat162float(hb));
        hi[p] = (uint32_t)__bfloat16_as_ushort(ha) |
                ((uint32_t)__bfloat16_as_ushort(hb) << 16);
        lo[p] = (uint32_t)__bfloat16_as_ushort(la) |
                ((uint32_t)__bfloat16_as_ushort(lb) << 16);
    }
}

// ---------------------------------------------------------------------------
// part[b][n] = sum_{k in chunk} A[b][k] * W[n][k]   (bf16 hi/lo compensated)
// z == 0: A=A0, W=W0, out=P0 + sp*strPS
// z >  0: l=z-1: A=A1+l*strA1, W=W1+l*strW1, out=P1 + l*strPL + sp*strPS
// ---------------------------------------------------------------------------
__global__ __launch_bounds__(NT, 2)
void mma_gemm(const float* __restrict__ A0, const float* __restrict__ W0,
              float* __restrict__ P0,
              const float* __restrict__ A1, const float* __restrict__ W1,
              float* __restrict__ P1,
              int K, int Kchunk, int N,
              long strA1, long strW1, long strPS, long strPL)
{
    extern __shared__ char dsm[];
    const uint32_t base = smem_u32(dsm);

    const int z  = blockIdx.z;
    const int sp = blockIdx.y;
    const float* Ag;
    const float* Wg;
    float* part;
    if (z == 0) {
        Ag = A0; Wg = W0; part = P0 + (long)sp * strPS;
    } else {
        const int l = z - 1;
        Ag = A1 + (long)l * strA1;
        Wg = W1 + (long)l * strW1;
        part = P1 + (long)l * strPL + (long)sp * strPS;
    }

    const int n0   = blockIdx.x * TM;
    const int tid  = threadIdx.x;
    const int wid  = tid >> 5;
    const int lane = tid & 31;

    const int fm = (wid & 3) * 32;   // warp feature offset (M)
    const int bn = (wid >> 2) * 32;  // warp batch offset (N)

    // fill mappings (bank-conflict-free: lanes cover consecutive rows)
    const int wr = tid & 127, wh = tid >> 7;   // W: row, 16-col half
    const int ar = tid & 63,  aq = tid >> 6;   // A: row, 8-col quarter

    // ldmatrix lane base offsets (bytes, within plane)
    uint32_t wrow[2], arow[2];
#pragma unroll
    for (int mt = 0; mt < 2; ++mt)
        wrow[mt] = (uint32_t)((fm + mt * 16 + ((lane >> 3) & 1) * 8 + (lane & 7)) * SWB
                              + (lane >> 4) * 16);
#pragma unroll
    for (int ng = 0; ng < 2; ++ng)
        arow[ng] = (uint32_t)((bn + ng * 16 + (lane >> 4) * 8 + (lane & 7)) * SWB
                              + ((lane >> 3) & 1) * 16);

    const int nst    = Kchunk / KC;
    const int k0base = sp * Kchunk;

    float4 wv[4], av[2];             // gmem staging (24 regs)
    float  d[2][4][4];
#pragma unroll
    for (int mt = 0; mt < 2; ++mt)
#pragma unroll
        for (int nt = 0; nt < 4; ++nt)
#pragma unroll
            for (int i = 0; i < 4; ++i) d[mt][nt][i] = 0.f;

    auto ldg_stage = [&](int st) {
        const int k0 = k0base + st * KC;
        const float4* ws = (const float4*)(Wg + (long)(n0 + wr) * K + k0 + wh * 16);
#pragma unroll
        for (int q = 0; q < 4; ++q) wv[q] = ws[q];
        const float4* as = (const float4*)(Ag + (long)ar * K + k0 + aq * 8);
#pragma unroll
        for (int q = 0; q < 2; ++q) av[q] = as[q];
    };

    auto store_stage = [&](int buf) {
        const uint32_t bb = base + (uint32_t)buf * BUFSZ;
        const uint32_t wdst = bb + (uint32_t)(wr * SWB + wh * 32);
#pragma unroll
        for (int g = 0; g < 2; ++g) {
            float f[8] = { wv[2*g].x, wv[2*g].y, wv[2*g].z, wv[2*g].w,
                           wv[2*g+1].x, wv[2*g+1].y, wv[2*g+1].z, wv[2*g+1].w };
            uint32_t hi[4], lo[4];
            cvt_hilo8(f, hi, lo);
            sts128(wdst + OFF_WH + g * 16, hi[0], hi[1], hi[2], hi[3]);
            sts128(wdst + OFF_WL + g * 16, lo[0], lo[1], lo[2], lo[3]);
        }
        {
            float f[8] = { av[0].x, av[0].y, av[0].z, av[0].w,
                           av[1].x, av[1].y, av[1].z, av[1].w };
            uint32_t hi[4], lo[4];
            cvt_hilo8(f, hi, lo);
            const uint32_t adst = bb + (uint32_t)(ar * SWB + aq * 16);
            sts128(adst + OFF_AH, hi[0], hi[1], hi[2], hi[3]);
            sts128(adst + OFF_AL, lo[0], lo[1], lo[2], lo[3]);
        }
    };

    auto compute_stage = [&](int buf) {
        const uint32_t bb = base + (uint32_t)buf * BUFSZ;
#pragma unroll
        for (int ks = 0; ks < KC / 16; ++ks) {
            const uint32_t kb = (uint32_t)(ks * 32);
            uint32_t whf[2][4], wlf[2][4], ahf[2][4], alf[2][4];
#pragma unroll
            for (int mt = 0; mt < 2; ++mt) {
                LDSM_X4(whf[mt], bb + OFF_WH + wrow[mt] + kb);
                LDSM_X4(wlf[mt], bb + OFF_WL + wrow[mt] + kb);
            }
#pragma unroll
            for (int ng = 0; ng < 2; ++ng) {
                LDSM_X4(ahf[ng], bb + OFF_AH + arow[ng] + kb);
                LDSM_X4(alf[ng], bb + OFF_AL + arow[ng] + kb);
            }
#pragma unroll
            for (int mt = 0; mt < 2; ++mt)
#pragma unroll
                for (int nt = 0; nt < 4; ++nt) {
                    const int ng = nt >> 1, hf = (nt & 1) * 2;
                    MMA_BF16(d[mt][nt], whf[mt], ahf[ng][hf], ahf[ng][hf + 1]);
                    MMA_BF16(d[mt][nt], wlf[mt], ahf[ng][hf], ahf[ng][hf + 1]);
                    MMA_BF16(d[mt][nt], whf[mt], alf[ng][hf], alf[ng][hf + 1]);
                }
        }
    };

    ldg_stage(0);
    store_stage(0);
    for (int st = 0; st < nst; ++st) {
        if (st + 1 < nst) ldg_stage(st + 1);
        __syncthreads();
        compute_stage(st & 1);
        if (st + 1 < nst) store_stage((st + 1) & 1);
    }

    // epilogue
#pragma unroll
    for (int mt = 0; mt < 2; ++mt)
#pragma unroll
        for (int nt = 0; nt < 4; ++nt)
#pragma unroll
            for (int i = 0; i < 4; ++i) {
                const int f = n0 + fm + mt * 16 + (lane >> 2) + (i >= 2 ? 8 : 0);
                const int b = bn + nt * 8 + (lane & 3) * 2 + (i & 1);
                part[(long)b * N + f] = d[mt][nt][i];
            }
}

// ---------------------------------------------------------------------------
__global__ void reduce_inp_kernel(const float* __restrict__ part,
                                  const float* __restrict__ bias,
                                  float* __restrict__ inp)
{
    const int idx = blockIdx.x * blockDim.x + threadIdx.x;
    if (idx >= B * H) return;
    float s = bias[idx % H];
#pragma unroll
    for (int k = 0; k < S_IN; ++k) s += part[(long)k * B * H + idx];
    inp[idx] = s;
}

// ---------------------------------------------------------------------------
__global__ void gate_kernel(const float* __restrict__ pgi, int Sgi,
                            const float* __restrict__ pgh, int Sgh,
                            const float* __restrict__ bih, const float* __restrict__ bhh,
                            const float* __restrict__ hprev, float* __restrict__ hid_out)
{
    const int idx = blockIdx.x * blockDim.x + threadIdx.x;
    if (idx >= B * H) return;
    const int b = idx / H;
    const int j = idx - b * H;
    const long base = (long)b * H3 + j;

    float ir = bih[j], iz = bih[j + H], in_ = bih[j + 2 * H];
    for (int s = 0; s < Sgi; ++s) {
        const float* p = pgi + (long)s * B * H3 + base;
        ir += p[0]; iz += p[H]; in_ += p[2 * H];
    }
    float hr = bhh[j], hz = bhh[j + H], hn = bhh[j + 2 * H];
    for (int s = 0; s < Sgh; ++s) {
        const float* p = pgh + (long)s * B * H3 + base;
        hr += p[0]; hz += p[H]; hn += p[2 * H];
    }

    const float r = 1.f / (1.f + __expf(-(ir + hr)));
    const float z = 1.f / (1.f + __expf(-(iz + hz)));
    const float n = tanhf(in_ + r * hn);
    hid_out[idx] = (1.f - z) * n + z * hprev[idx];
}

// ---------------------------------------------------------------------------
__global__ void h2o_kernel(const float* __restrict__ h, const float* __restrict__ Wo,
                           const float* __restrict__ bo, float* __restrict__ out)
{
    const int gw   = (blockIdx.x * blockDim.x + threadIdx.x) >> 5;
    const int lane = threadIdx.x & 31;
    if (gw >= B * O) return;
    const int b = gw / O;
    const int o = gw - b * O;

    const float4* hv = (const float4*)(h  + (long)b * H);
    const float4* wv = (const float4*)(Wo + (long)o * H);
    float s = 0.f;
#pragma unroll
    for (int i = lane; i < H / 4; i += 32) {
        const float4 a = hv[i], w = wv[i];
        s += a.x * w.x + a.y * w.y + a.z * w.z + a.w * w.w;
    }
#pragma unroll
    for (int off = 16; off; off >>= 1) s += __shfl_xor_sync(0xFFFFFFFFu, s, off);
    if (lane == 0) out[gw] = s + bo[o];
}

// ---------------------------------------------------------------------------
extern "C" void kernel_launch(void* const* d_in, const int* in_sizes, int n_in,
                              void* d_out, int out_size)
{
    const float* x      = (const float*)d_in[0];
    const float* hidden = (const float*)d_in[1];
    const float* w_i2h  = (const float*)d_in[2];
    const float* b_i2h  = (const float*)d_in[3];
    const float* w_ih   = (const float*)d_in[4];
    const float* w_hh   = (const float*)d_in[5];
    const float* b_ih   = (const float*)d_in[6];
    const float* b_hh   = (const float*)d_in[7];
    const float* w_h2o  = (const float*)d_in[8];
    const float* b_h2o  = (const float*)d_in[9];

    float* out        = (float*)d_out;       // [B, O]
    float* out_hidden = out + B * O;         // [L, B, H]

    float *inp, *pin, *pgh, *pgi;
    cudaGetSymbolAddress((void**)&inp, g_inp);
    cudaGetSymbolAddress((void**)&pin, g_pin);
    cudaGetSymbolAddress((void**)&pgh, g_pgh);
    cudaGetSymbolAddress((void**)&pgi, g_pgi);

    cudaFuncSetAttribute(mma_gemm, cudaFuncAttributeMaxDynamicSharedMemorySize, DSMEM);

    // 1) i2h partials: K=320, 5 splits of 64 (2 stages), grid (12,5,1)=60 blocks
    mma_gemm<<<dim3(H / TM, S_IN, 1), NT, DSMEM>>>(
        x, w_i2h, pin, nullptr, nullptr, nullptr,
        I, I / S_IN, H, 0, 0, (long)B * H, 0);
    reduce_inp_kernel<<<(B * H + 255) / 256, 256>>>(pin, b_i2h, inp);

    // 2) merged: z=0 -> gi layer0 (A=inp, W=w_ih[0]); z=1..3 -> gh layer z-1
    //    grid (36, 2, 4) = 288 blocks, Kchunk=768 (24 stages)
    mma_gemm<<<dim3(H3 / TM, S_MG, 4), NT, DSMEM>>>(
        inp, w_ih, pgi, hidden, w_hh, pgh,
        H, H / S_MG, H3,
        (long)B * H, (long)H3 * H, (long)B * H3, (long)S_MG * B * H3);

    // 3) gate layer 0 (gi split=2 from merged launch)
    gate_kernel<<<(B * H + 255) / 256, 256>>>(
        pgi, S_MG, pgh, S_MG,
        b_ih, b_hh, hidden, out_hidden);

    // 4) serial chain layers 1,2: gi split=8 (288 blocks, 6 stages) + gate
    for (int l = 1; l < L; ++l) {
        mma_gemm<<<dim3(H3 / TM, S_GI, 1), NT, DSMEM>>>(
            out_hidden + (long)(l - 1) * B * H, w_ih + (long)l * H3 * H, pgi,
            nullptr, nullptr, nullptr,
            H, H / S_GI, H3, 0, 0, (long)B * H3, 0);
        gate_kernel<<<(B * H + 255) / 256, 256>>>(
            pgi, S_GI, pgh + (long)l * S_MG * B * H3, S_MG,
            b_ih + (long)l * H3, b_hh + (long)l * H3,
            hidden + (long)l * B * H, out_hidden + (long)l * B * H);
    }

    // 5) output = h2 @ w_h2o^T + b_h2o
    h2o_kernel<<<(B * O * 32 + 255) / 256, 256>>>(
        out_hidden + (long)2 * B * H, w_h2o, b_h2o, out);
}